// round 4
// baseline (speedup 1.0000x reference)
#include <cuda_runtime.h>

#define M_PTS 5151
#define HIDN  256
#define BB    16
#define SS    256
#define TT    1024
#define NBLK_M 41          // ceil(5151/128) scan blocks per batch
#define CUT 0.018f

// Output layout: concatenated (b_out, density, m, initial_states, mesh)
#define OFF_BOUT 0
#define OFF_D    16384                    // 16*1024
#define OFF_M    (OFF_D + BB*M_PTS)       // 98800
#define OFF_IS   (OFF_M + BB*TT)          // 115184
#define OFF_MESH (OFF_IS + BB*M_PTS)      // 197600

// ---------------- scratch (device globals; no allocation) ----------------
__device__ float g_x[5248*HIDN];
__device__ float g_y[5248*HIDN];
__device__ float g_density[M_PTS];
__device__ float g_cwc[BB*HIDN];
__device__ float g_init[BB*M_PTS];
__device__ float g_bpart[BB*NBLK_M*TT];

__device__ __forceinline__ float fast_tanh(float x) {
    float r;
    asm("tanh.approx.f32 %0, %1;" : "=f"(r) : "f"(x));
    return r;
}

// ---------------- density input layer: x = relu(mesh @ Win + bin) --------
__global__ void k_dens_in(const float* __restrict__ mesh,
                          const float* __restrict__ Win,
                          const float* __restrict__ bin) {
    int m = blockIdx.x;
    int j = threadIdx.x;
    float be = mesh[2*m], al = mesh[2*m+1];
    float v = be*Win[j] + al*Win[HIDN+j] + bin[j];
    g_x[m*HIDN + j] = fmaxf(v, 0.f);
}

// ---------------- residual layer: Y = X + relu(X @ W + b) ----------------
// 64x64 tile, in-block split-K: 256 threads, two 128-thread halves each do
// K=128 with BK=16 / 8x4 micro-tile / register prefetch; combine via smem.
__global__ void __launch_bounds__(256) k_res(const float* __restrict__ W,
                                             const float* __restrict__ bias,
                                             int flip) {
    const float* X = flip ? g_y : g_x;
    float*       Y = flip ? g_x : g_y;

    // [As0 16x68 | As1 16x68 | Bs0 16x64 | Bs1 16x64] ; comb aliases (64x65)
    __shared__ __align__(16) float sbuf[4224];

    int tid  = threadIdx.x;
    int half = tid >> 7;          // 0 or 1 (K-half)
    int t    = tid & 127;
    float* As = sbuf + half*1088;          // [k][row] stride 68
    float* Bs = sbuf + 2176 + half*1024;   // [k][col] stride 64

    int bm = blockIdx.x * 64, bn = blockIdx.y * 64;
    int tx = t & 15;        // 16 col groups (4 cols each)
    int ty = t >> 4;        // 8 row groups (8 rows each)

    float acc[8][4];
#pragma unroll
    for (int i = 0; i < 8; i++)
#pragma unroll
        for (int j = 0; j < 4; j++) acc[i][j] = 0.f;

    int arow = t & 63;
    int acol = (t >> 6) * 8;
    int gra  = bm + arow;
    bool av  = gra < M_PTS;
    int kbase = half * 128;
    const float* Xa = X + (size_t)(av ? gra : 0) * HIDN + kbase + acol;
    int bkr0 = t >> 4;              // k 0..7
    int bc   = (t & 15) * 4;
    const float* Wb = W + (size_t)(kbase + bkr0) * HIDN + bn + bc;

    float4 z4 = make_float4(0.f,0.f,0.f,0.f);
    float4 pa0 = av ? *(const float4*)(Xa + 0) : z4;
    float4 pa1 = av ? *(const float4*)(Xa + 4) : z4;
    float4 pb0 = *(const float4*)(Wb);
    float4 pb1 = *(const float4*)(Wb + 8*HIDN);

    for (int k0 = 0; k0 < 128; k0 += 16) {
        As[(acol+0)*68 + arow] = pa0.x;
        As[(acol+1)*68 + arow] = pa0.y;
        As[(acol+2)*68 + arow] = pa0.z;
        As[(acol+3)*68 + arow] = pa0.w;
        As[(acol+4)*68 + arow] = pa1.x;
        As[(acol+5)*68 + arow] = pa1.y;
        As[(acol+6)*68 + arow] = pa1.z;
        As[(acol+7)*68 + arow] = pa1.w;
        *(float4*)&Bs[bkr0*64 + bc]     = pb0;
        *(float4*)&Bs[(bkr0+8)*64 + bc] = pb1;
        __syncthreads();

        if (k0 + 16 < 128) {
            const float* Xn = Xa + k0 + 16;
            const float* Wn = Wb + (size_t)(k0 + 16) * HIDN;
            pa0 = av ? *(const float4*)(Xn + 0) : z4;
            pa1 = av ? *(const float4*)(Xn + 4) : z4;
            pb0 = *(const float4*)(Wn);
            pb1 = *(const float4*)(Wn + 8*HIDN);
        }

#pragma unroll
        for (int kk = 0; kk < 16; kk++) {
            float4 a0 = *(const float4*)&As[kk*68 + ty*8];
            float4 a1 = *(const float4*)&As[kk*68 + ty*8 + 4];
            float4 b0 = *(const float4*)&Bs[kk*64 + tx*4];
            float a[8] = {a0.x,a0.y,a0.z,a0.w,a1.x,a1.y,a1.z,a1.w};
            float b[4] = {b0.x,b0.y,b0.z,b0.w};
#pragma unroll
            for (int i = 0; i < 8; i++)
#pragma unroll
                for (int j = 0; j < 4; j++)
                    acc[i][j] = fmaf(a[i], b[j], acc[i][j]);
        }
        __syncthreads();
    }

    // combine halves through smem (aliases As/Bs; all reads done at last barrier)
    float* comb = sbuf;   // 64 x 65
    if (half == 1) {
#pragma unroll
        for (int i = 0; i < 8; i++)
#pragma unroll
            for (int j = 0; j < 4; j++)
                comb[(ty*8 + i)*65 + tx*4 + j] = acc[i][j];
    }
    __syncthreads();

    if (half == 0) {
        int gc0 = bn + tx*4;
        float4 bz = *(const float4*)&bias[gc0];
        float bv[4] = {bz.x, bz.y, bz.z, bz.w};
#pragma unroll
        for (int i = 0; i < 8; i++) {
            int gr = bm + ty*8 + i;
            if (gr < M_PTS) {
                float4 xv = *(const float4*)&X[gr*HIDN + gc0];
                const float* cr = &comb[(ty*8 + i)*65 + tx*4];
                float4 o;
                o.x = xv.x + fmaxf(acc[i][0] + cr[0] + bv[0], 0.f);
                o.y = xv.y + fmaxf(acc[i][1] + cr[1] + bv[1], 0.f);
                o.z = xv.z + fmaxf(acc[i][2] + cr[2] + bv[2], 0.f);
                o.w = xv.w + fmaxf(acc[i][3] + cr[3] + bv[3], 0.f);
                *(float4*)&Y[gr*HIDN + gc0] = o;
            }
        }
    }
}

// ---------------- density output: sigmoid(x @ Wout + bout) ---------------
__global__ void k_dens_out(const float* __restrict__ Wout,
                           const float* __restrict__ bout) {
    int w = blockIdx.x*8 + (threadIdx.x >> 5);
    int lane = threadIdx.x & 31;
    if (w >= M_PTS) return;
    float acc = 0.f;
#pragma unroll
    for (int i = 0; i < 8; i++)
        acc += g_y[w*HIDN + lane + i*32] * Wout[lane + i*32];
#pragma unroll
    for (int o = 16; o; o >>= 1) acc += __shfl_xor_sync(0xffffffffu, acc, o);
    if (lane == 0) {
        float z = acc + bout[0];
        g_density[w] = 1.f / (1.f + __expf(-z));
    }
}

// ---------------- encoder ctx + ctx @ Wc (fused) ----------------
__global__ void k_ctxw(const float* __restrict__ enc,
                       const float* __restrict__ mask,
                       const float* __restrict__ Ws,
                       const float* __restrict__ bs,
                       const float* __restrict__ Wc) {
    int b = blockIdx.x;
    int j = threadIdx.x;
    __shared__ float se[2*SS];
    __shared__ float sm[SS];
    __shared__ float sctx[HIDN];
    for (int i = j; i < 2*SS; i += 256) se[i] = enc[b*2*SS + i];
    for (int i = j; i < SS;   i += 256) sm[i] = mask[b*SS + i];
    __syncthreads();
    float w0 = Ws[j], w1 = Ws[HIDN + j], bj = bs[j];
    float acc = 0.f, msum = 0.f;
    for (int s = 0; s < SS; s++) {
        float mk = sm[s];
        msum += mk;
        float v = fmaxf(se[2*s]*w0 + se[2*s+1]*w1 + bj, 0.f);
        acc += mk * v;
    }
    sctx[j] = acc / fmaxf(msum, 1.f);
    __syncthreads();
    float a2 = 0.f;
    for (int k = 0; k < HIDN; k++) a2 += sctx[k] * Wc[k*HIDN + j];
    g_cwc[b*HIDN + j] = a2;
}

// ------- initial states + density/mesh replication; 4 points/thread ------
__global__ void k_init(const float* __restrict__ mesh,
                       const float* __restrict__ Wm,
                       const float* __restrict__ bm,
                       const float* __restrict__ Wo,
                       const float* __restrict__ bo,
                       float* __restrict__ out) {
    int b = blockIdx.y;
    int j = threadIdx.x;
    __shared__ __align__(16) float sW0[HIDN], sW1[HIDN], sW2[HIDN], sWo[HIDN], sC[HIDN];
    sW0[j] = Wm[j];
    sW1[j] = Wm[HIDN + j];
    sW2[j] = Wm[2*HIDN + j];
    sWo[j] = Wo[j];
    sC[j]  = g_cwc[b*HIDN + j] + bm[j];
    __syncthreads();

    int m[4]; bool v[4];
    float be[4], al[4], d[4], acc[4];
#pragma unroll
    for (int q = 0; q < 4; q++) {
        m[q] = blockIdx.x*1024 + q*256 + j;
        v[q] = m[q] < M_PTS;
        int mm = v[q] ? m[q] : 0;
        be[q] = mesh[2*mm];
        al[q] = mesh[2*mm + 1];
        d[q]  = g_density[mm];
        acc[q] = 0.f;
    }

    const float4* w0 = (const float4*)sW0;
    const float4* w1 = (const float4*)sW1;
    const float4* w2 = (const float4*)sW2;
    const float4* wo = (const float4*)sWo;
    const float4* cc = (const float4*)sC;
#pragma unroll 2
    for (int qq = 0; qq < HIDN/4; qq++) {
        float4 a0 = w0[qq], a1 = w1[qq], a2 = w2[qq], ao = wo[qq], ac = cc[qq];
#pragma unroll
        for (int q = 0; q < 4; q++) {
            acc[q] += fmaxf(ac.x + be[q]*a0.x + al[q]*a1.x + d[q]*a2.x, 0.f) * ao.x;
            acc[q] += fmaxf(ac.y + be[q]*a0.y + al[q]*a1.y + d[q]*a2.y, 0.f) * ao.y;
            acc[q] += fmaxf(ac.z + be[q]*a0.z + al[q]*a1.z + d[q]*a2.z, 0.f) * ao.z;
            acc[q] += fmaxf(ac.w + be[q]*a0.w + al[q]*a1.w + d[q]*a2.w, 0.f) * ao.w;
        }
    }
    float bo0 = bo[0];
#pragma unroll
    for (int q = 0; q < 4; q++) {
        if (!v[q]) continue;
        float is = tanhf(acc[q] + bo0);
        g_init[b*M_PTS + m[q]] = is;
        out[OFF_IS + (size_t)b*M_PTS + m[q]] = is;
        out[OFF_D  + (size_t)b*M_PTS + m[q]] = d[q];
        ((float2*)out)[(OFF_MESH >> 1) + (size_t)b*M_PTS + m[q]] = make_float2(be[q], al[q]);
    }
}

// ---------------- relay scan: 64 threads, 2 points/thread ----------------
__global__ void k_scan(const float* __restrict__ dec,
                       const float* __restrict__ mesh) {
    __shared__ float sh_h[TT];
    __shared__ float sh_part[2][TT];
    int b = blockIdx.y;
    int tid = threadIdx.x;        // 0..63
    int m0 = blockIdx.x*128 + tid;
    int m1 = m0 + 64;

    for (int t = tid; t < TT; t += 64) sh_h[t] = dec[b*TT + t];

    bool v0 = m0 < M_PTS, v1 = m1 < M_PTS;
    float be0 = v0 ? mesh[2*m0]   : -2.f;
    float al0 = v0 ? mesh[2*m0+1] :  2.f;
    float d0  = v0 ? g_density[m0] : 0.f;
    float s0  = v0 ? g_init[b*M_PTS + m0] : 0.f;
    float be1 = v1 ? mesh[2*m1]   : -2.f;
    float al1 = v1 ? mesh[2*m1+1] :  2.f;
    float d1  = v1 ? g_density[m1] : 0.f;
    float s1  = v1 ? g_init[b*M_PTS + m1] : 0.f;
    __syncthreads();

    int wid = tid >> 5, lane = tid & 31;
    float* myrow = sh_part[wid];

    for (int t = 0; t < TT; t++) {
        float ht = sh_h[t];

        float xu0 = ht - al0;
        float xd0 = be0 - ht;
        float xu1 = ht - al1;
        float xd1 = be1 - ht;

        bool nearany = (fabsf(xu0) < CUT) | (fabsf(xd0) < CUT) |
                       (fabsf(xu1) < CUT) | (fabsf(xd1) < CUT);
        if (__any_sync(0xffffffffu, nearany)) {
            float wu0 = 0.5f*fast_tanh(500.f*xu0) + 0.5f;
            float wd0 = 0.5f*fast_tanh(500.f*xd0) + 0.5f;
            s0 += wu0 * (1.f - s0);
            s0 += wd0 * (-1.f - s0);
            float wu1 = 0.5f*fast_tanh(500.f*xu1) + 0.5f;
            float wd1 = 0.5f*fast_tanh(500.f*xd1) + 0.5f;
            s1 += wu1 * (1.f - s1);
            s1 += wd1 * (-1.f - s1);
        } else {
            if (xu0 > 0.f) s0 = 1.f;
            if (xd0 > 0.f) s0 = -1.f;
            if (xu1 > 0.f) s1 = 1.f;
            if (xd1 > 0.f) s1 = -1.f;
        }

        float c = d0*s0 + d1*s1;
        c += __shfl_xor_sync(0xffffffffu, c, 16);
        c += __shfl_xor_sync(0xffffffffu, c, 8);
        c += __shfl_xor_sync(0xffffffffu, c, 4);
        c += __shfl_xor_sync(0xffffffffu, c, 2);
        c += __shfl_xor_sync(0xffffffffu, c, 1);
        if (lane == 0) myrow[t] = c;
    }
    __syncthreads();

    for (int t = tid; t < TT; t += 64) {
        float a = sh_part[0][t] + sh_part[1][t];
        g_bpart[((size_t)b*NBLK_M + blockIdx.x)*TT + t] = a;
    }
}

// ---------------- final: dsum + m + b_out ----------------
__global__ void k_final(const float* __restrict__ dec,
                        const float* __restrict__ hraw,
                        const float* __restrict__ mraw,
                        const float* __restrict__ oraw,
                        float* __restrict__ out) {
    __shared__ float sred[256];
    int tid = threadIdx.x;
    // per-block identical deterministic dsum
    float a = 0.f;
    for (int i = tid; i < M_PTS; i += 256) a += g_density[i];
    sred[tid] = a;
    __syncthreads();
    for (int o = 128; o; o >>= 1) {
        if (tid < o) sred[tid] += sred[tid + o];
        __syncthreads();
    }
    float dsum = sred[0];

    int i = blockIdx.x*256 + tid;   // 0..16383
    int b = i >> 10, t = i & 1023;
    float acc = 0.f;
#pragma unroll
    for (int k = 0; k < NBLK_M; k++)
        acc += g_bpart[((size_t)b*NBLK_M + k)*TT + t];
    float mv = acc / dsum;
    float h = dec[i];
    float hs  = 10.f / (1.f + __expf(-hraw[0]));
    float ms  = 10.f / (1.f + __expf(-mraw[0]));
    float off = -10.f + 20.f / (1.f + __expf(-oraw[0]));
    out[OFF_BOUT + i] = hs*h + ms*mv + off;
    out[OFF_M + i] = mv;
}

// ---------------- launch ----------------
extern "C" void kernel_launch(void* const* d_in, const int* in_sizes, int n_in,
                              void* d_out, int out_size) {
    (void)in_sizes; (void)n_in; (void)out_size;
    const float* enc   = (const float*)d_in[0];
    const float* dec   = (const float*)d_in[1];
    const float* msk   = (const float*)d_in[2];
    const float* mesh  = (const float*)d_in[3];
    const float* dWin  = (const float*)d_in[4];
    const float* dbin  = (const float*)d_in[5];
    const float* dWr   = (const float*)d_in[6];
    const float* dbr   = (const float*)d_in[7];
    const float* dWout = (const float*)d_in[8];
    const float* dbout = (const float*)d_in[9];
    const float* eWs   = (const float*)d_in[10];
    const float* ebs   = (const float*)d_in[11];
    const float* eWm   = (const float*)d_in[12];
    const float* eWc   = (const float*)d_in[13];
    const float* ebm   = (const float*)d_in[14];
    const float* eWo   = (const float*)d_in[15];
    const float* ebo   = (const float*)d_in[16];
    const float* hraw  = (const float*)d_in[17];
    const float* mraw  = (const float*)d_in[18];
    const float* oraw  = (const float*)d_in[19];
    float* out = (float*)d_out;

    // density MLP
    k_dens_in<<<M_PTS, 256>>>(mesh, dWin, dbin);
    dim3 gres(81, 4);
    k_res<<<gres, 256>>>(dWr + 0*HIDN*HIDN, dbr + 0*HIDN, 0);  // x -> y
    k_res<<<gres, 256>>>(dWr + 1*HIDN*HIDN, dbr + 1*HIDN, 1);  // y -> x
    k_res<<<gres, 256>>>(dWr + 2*HIDN*HIDN, dbr + 2*HIDN, 0);  // x -> y
    k_dens_out<<<644, 256>>>(dWout, dbout);

    // encoder + initial states (+ density/mesh output replication)
    k_ctxw<<<BB, 256>>>(enc, msk, eWs, ebs, eWc);
    dim3 ginit(6, BB);
    k_init<<<ginit, 256>>>(mesh, eWm, ebm, eWo, ebo, out);

    // relay scan + final (final also computes dsum)
    dim3 gscan(NBLK_M, BB);
    k_scan<<<gscan, 64>>>(dec, mesh);
    k_final<<<64, 256>>>(dec, hraw, mraw, oraw, out);
}

// round 5
// speedup vs baseline: 1.4320x; 1.4320x over previous
#include <cuda_runtime.h>

#define M_PTS 5151
#define HIDN  256
#define BB    16
#define SS    256
#define TT    1024
#define NBLK_M 21          // ceil(5151/256) scan blocks per batch
#define TC     64          // scan time-chunk
#define CUT 0.018f

// Output layout: concatenated (b_out, density, m, initial_states, mesh)
#define OFF_BOUT 0
#define OFF_D    16384                    // 16*1024
#define OFF_M    (OFF_D + BB*M_PTS)       // 98800
#define OFF_IS   (OFF_M + BB*TT)          // 115184
#define OFF_MESH (OFF_IS + BB*M_PTS)      // 197600

// ---------------- scratch (device globals; no allocation) ----------------
__device__ float g_x[5248*HIDN];
__device__ float g_y[5248*HIDN];
__device__ float g_density[M_PTS];
__device__ float g_cwc[BB*HIDN];
__device__ float g_init[BB*M_PTS];
__device__ float g_bpart[BB*NBLK_M*TT];

__device__ __forceinline__ float fast_tanh(float x) {
    float r;
    asm("tanh.approx.f32 %0, %1;" : "=f"(r) : "f"(x));
    return r;
}

// ---------------- density input layer: x = relu(mesh @ Win + bin) --------
__global__ void k_dens_in(const float* __restrict__ mesh,
                          const float* __restrict__ Win,
                          const float* __restrict__ bin) {
    int m = blockIdx.x;
    int j = threadIdx.x;
    float be = mesh[2*m], al = mesh[2*m+1];
    float v = be*Win[j] + al*Win[HIDN+j] + bin[j];
    g_x[m*HIDN + j] = fmaxf(v, 0.f);
}

// ---------------- residual layer: Y = X + relu(X @ W + b) ----------------
// 64x64 tile, BK=16, 128 threads, 8x4 micro-tile, register prefetch. (R3 best)
__global__ void __launch_bounds__(128) k_res(const float* __restrict__ W,
                                             const float* __restrict__ bias,
                                             int flip) {
    const float* X = flip ? g_y : g_x;
    float*       Y = flip ? g_x : g_y;

    __shared__ __align__(16) float As[16][68];   // [k][row]
    __shared__ __align__(16) float Bs[16][64];   // [k][col]

    int bm = blockIdx.x * 64, bn = blockIdx.y * 64;
    int tid = threadIdx.x;
    int tx = tid & 15;
    int ty = tid >> 4;

    float acc[8][4];
#pragma unroll
    for (int i = 0; i < 8; i++)
#pragma unroll
        for (int j = 0; j < 4; j++) acc[i][j] = 0.f;

    int arow = tid & 63;
    int acol = (tid >> 6) * 8;
    int gra  = bm + arow;
    bool av  = gra < M_PTS;
    const float* Xa = X + (size_t)(av ? gra : 0) * HIDN + acol;
    int bkr0 = tid >> 4;
    int bc   = (tid & 15) * 4;
    const float* Wb = W + (size_t)bkr0 * HIDN + bn + bc;

    float4 z4 = make_float4(0.f,0.f,0.f,0.f);
    float4 pa0 = av ? *(const float4*)(Xa + 0) : z4;
    float4 pa1 = av ? *(const float4*)(Xa + 4) : z4;
    float4 pb0 = *(const float4*)(Wb);
    float4 pb1 = *(const float4*)(Wb + 8*HIDN);

    for (int k0 = 0; k0 < HIDN; k0 += 16) {
        As[acol+0][arow] = pa0.x;
        As[acol+1][arow] = pa0.y;
        As[acol+2][arow] = pa0.z;
        As[acol+3][arow] = pa0.w;
        As[acol+4][arow] = pa1.x;
        As[acol+5][arow] = pa1.y;
        As[acol+6][arow] = pa1.z;
        As[acol+7][arow] = pa1.w;
        *(float4*)&Bs[bkr0    ][bc] = pb0;
        *(float4*)&Bs[bkr0 + 8][bc] = pb1;
        __syncthreads();

        if (k0 + 16 < HIDN) {
            const float* Xn = Xa + k0 + 16;
            const float* Wn = Wb + (size_t)(k0 + 16) * HIDN;
            pa0 = av ? *(const float4*)(Xn + 0) : z4;
            pa1 = av ? *(const float4*)(Xn + 4) : z4;
            pb0 = *(const float4*)(Wn);
            pb1 = *(const float4*)(Wn + 8*HIDN);
        }

#pragma unroll
        for (int kk = 0; kk < 16; kk++) {
            float4 a0 = *(const float4*)&As[kk][ty*8];
            float4 a1 = *(const float4*)&As[kk][ty*8 + 4];
            float4 b0 = *(const float4*)&Bs[kk][tx*4];
            float a[8] = {a0.x,a0.y,a0.z,a0.w,a1.x,a1.y,a1.z,a1.w};
            float b[4] = {b0.x,b0.y,b0.z,b0.w};
#pragma unroll
            for (int i = 0; i < 8; i++)
#pragma unroll
                for (int j = 0; j < 4; j++)
                    acc[i][j] = fmaf(a[i], b[j], acc[i][j]);
        }
        __syncthreads();
    }

    int gc0 = bn + tx*4;
    float4 bz = *(const float4*)&bias[gc0];
    float bv[4] = {bz.x, bz.y, bz.z, bz.w};
#pragma unroll
    for (int i = 0; i < 8; i++) {
        int gr = bm + ty*8 + i;
        if (gr < M_PTS) {
            float4 xv = *(const float4*)&X[gr*HIDN + gc0];
            float4 o;
            o.x = xv.x + fmaxf(acc[i][0] + bv[0], 0.f);
            o.y = xv.y + fmaxf(acc[i][1] + bv[1], 0.f);
            o.z = xv.z + fmaxf(acc[i][2] + bv[2], 0.f);
            o.w = xv.w + fmaxf(acc[i][3] + bv[3], 0.f);
            *(float4*)&Y[gr*HIDN + gc0] = o;
        }
    }
}

// ---------------- density output: sigmoid(x @ Wout + bout) ---------------
__global__ void k_dens_out(const float* __restrict__ Wout,
                           const float* __restrict__ bout) {
    int w = blockIdx.x*8 + (threadIdx.x >> 5);
    int lane = threadIdx.x & 31;
    if (w >= M_PTS) return;
    float acc = 0.f;
#pragma unroll
    for (int i = 0; i < 8; i++)
        acc += g_y[w*HIDN + lane + i*32] * Wout[lane + i*32];
#pragma unroll
    for (int o = 16; o; o >>= 1) acc += __shfl_xor_sync(0xffffffffu, acc, o);
    if (lane == 0) {
        float z = acc + bout[0];
        g_density[w] = 1.f / (1.f + __expf(-z));
    }
}

// ---------------- encoder ctx + ctx @ Wc (fused) ----------------
__global__ void k_ctxw(const float* __restrict__ enc,
                       const float* __restrict__ mask,
                       const float* __restrict__ Ws,
                       const float* __restrict__ bs,
                       const float* __restrict__ Wc) {
    int b = blockIdx.x;
    int j = threadIdx.x;
    __shared__ float se[2*SS];
    __shared__ float sm[SS];
    __shared__ float sctx[HIDN];
    for (int i = j; i < 2*SS; i += 256) se[i] = enc[b*2*SS + i];
    for (int i = j; i < SS;   i += 256) sm[i] = mask[b*SS + i];
    __syncthreads();
    float w0 = Ws[j], w1 = Ws[HIDN + j], bj = bs[j];
    float acc = 0.f, msum = 0.f;
    for (int s = 0; s < SS; s++) {
        float mk = sm[s];
        msum += mk;
        float v = fmaxf(se[2*s]*w0 + se[2*s+1]*w1 + bj, 0.f);
        acc += mk * v;
    }
    sctx[j] = acc / fmaxf(msum, 1.f);
    __syncthreads();
    float a2 = 0.f;
    for (int k = 0; k < HIDN; k++) a2 += sctx[k] * Wc[k*HIDN + j];
    g_cwc[b*HIDN + j] = a2;
}

// ------- initial states + density/mesh replication; 4 points/thread ------
__global__ void k_init(const float* __restrict__ mesh,
                       const float* __restrict__ Wm,
                       const float* __restrict__ bm,
                       const float* __restrict__ Wo,
                       const float* __restrict__ bo,
                       float* __restrict__ out) {
    int b = blockIdx.y;
    int j = threadIdx.x;
    __shared__ __align__(16) float sW0[HIDN], sW1[HIDN], sW2[HIDN], sWo[HIDN], sC[HIDN];
    sW0[j] = Wm[j];
    sW1[j] = Wm[HIDN + j];
    sW2[j] = Wm[2*HIDN + j];
    sWo[j] = Wo[j];
    sC[j]  = g_cwc[b*HIDN + j] + bm[j];
    __syncthreads();

    int m[4]; bool v[4];
    float be[4], al[4], d[4], acc[4];
#pragma unroll
    for (int q = 0; q < 4; q++) {
        m[q] = blockIdx.x*1024 + q*256 + j;
        v[q] = m[q] < M_PTS;
        int mm = v[q] ? m[q] : 0;
        be[q] = mesh[2*mm];
        al[q] = mesh[2*mm + 1];
        d[q]  = g_density[mm];
        acc[q] = 0.f;
    }

    const float4* w0 = (const float4*)sW0;
    const float4* w1 = (const float4*)sW1;
    const float4* w2 = (const float4*)sW2;
    const float4* wo = (const float4*)sWo;
    const float4* cc = (const float4*)sC;
#pragma unroll 2
    for (int qq = 0; qq < HIDN/4; qq++) {
        float4 a0 = w0[qq], a1 = w1[qq], a2 = w2[qq], ao = wo[qq], ac = cc[qq];
#pragma unroll
        for (int q = 0; q < 4; q++) {
            acc[q] += fmaxf(ac.x + be[q]*a0.x + al[q]*a1.x + d[q]*a2.x, 0.f) * ao.x;
            acc[q] += fmaxf(ac.y + be[q]*a0.y + al[q]*a1.y + d[q]*a2.y, 0.f) * ao.y;
            acc[q] += fmaxf(ac.z + be[q]*a0.z + al[q]*a1.z + d[q]*a2.z, 0.f) * ao.z;
            acc[q] += fmaxf(ac.w + be[q]*a0.w + al[q]*a1.w + d[q]*a2.w, 0.f) * ao.w;
        }
    }
    float bo0 = bo[0];
#pragma unroll
    for (int q = 0; q < 4; q++) {
        if (!v[q]) continue;
        float is = tanhf(acc[q] + bo0);
        g_init[b*M_PTS + m[q]] = is;
        out[OFF_IS + (size_t)b*M_PTS + m[q]] = is;
        out[OFF_D  + (size_t)b*M_PTS + m[q]] = d[q];
        ((float2*)out)[(OFF_MESH >> 1) + (size_t)b*M_PTS + m[q]] = make_float2(be[q], al[q]);
    }
}

// ------- relay scan: 128 threads, 2 points/thread, chunked reduce --------
__global__ void __launch_bounds__(128) k_scan(const float* __restrict__ dec,
                                              const float* __restrict__ mesh) {
    __shared__ float sh_h[TT];
    __shared__ float tile[128*(TC+1)];
    __shared__ float aux[2][TC];
    int b = blockIdx.y;
    int tid = threadIdx.x;        // 0..127
    int m0 = blockIdx.x*256 + tid;
    int m1 = m0 + 128;

    for (int t = tid; t < TT; t += 128) sh_h[t] = dec[b*TT + t];

    bool v0 = m0 < M_PTS, v1 = m1 < M_PTS;
    float be0 = v0 ? mesh[2*m0]   : -2.f;
    float al0 = v0 ? mesh[2*m0+1] :  2.f;
    float d0  = v0 ? g_density[m0] : 0.f;
    float s0  = v0 ? g_init[b*M_PTS + m0] : 0.f;
    float be1 = v1 ? mesh[2*m1]   : -2.f;
    float al1 = v1 ? mesh[2*m1+1] :  2.f;
    float d1  = v1 ? g_density[m1] : 0.f;
    float s1  = v1 ? g_init[b*M_PTS + m1] : 0.f;
    __syncthreads();

    float* myrow = &tile[tid*(TC+1)];
    int rcol  = tid & (TC-1);          // reduce column
    int rbase = (tid >> 6) * 64;       // reduce row half (0 or 64)
    float* gout = &g_bpart[((size_t)b*NBLK_M + blockIdx.x)*TT];

    for (int c0 = 0; c0 < TT; c0 += TC) {
#pragma unroll 4
        for (int tt = 0; tt < TC; tt++) {
            float ht = sh_h[c0 + tt];
            float xu0 = ht - al0;
            float xd0 = be0 - ht;
            float xu1 = ht - al1;
            float xd1 = be1 - ht;

            bool nearany = (fabsf(xu0) < CUT) | (fabsf(xd0) < CUT) |
                           (fabsf(xu1) < CUT) | (fabsf(xd1) < CUT);
            if (__any_sync(0xffffffffu, nearany)) {
                float wu0 = 0.5f*fast_tanh(500.f*xu0) + 0.5f;
                float wd0 = 0.5f*fast_tanh(500.f*xd0) + 0.5f;
                s0 += wu0 * (1.f - s0);
                s0 += wd0 * (-1.f - s0);
                float wu1 = 0.5f*fast_tanh(500.f*xu1) + 0.5f;
                float wd1 = 0.5f*fast_tanh(500.f*xd1) + 0.5f;
                s1 += wu1 * (1.f - s1);
                s1 += wd1 * (-1.f - s1);
            } else {
                if (xu0 > 0.f) s0 = 1.f;
                if (xd0 > 0.f) s0 = -1.f;
                if (xu1 > 0.f) s1 = 1.f;
                if (xd1 > 0.f) s1 = -1.f;
            }
            myrow[tt] = d0*s0 + d1*s1;
        }
        __syncthreads();
        // reduce 128 rows x TC cols: each thread sums 64 rows of one column
        float a = 0.f;
#pragma unroll 8
        for (int i = 0; i < 64; i++)
            a += tile[(rbase + i)*(TC+1) + rcol];
        aux[tid >> 6][rcol] = a;
        __syncthreads();
        if (tid < TC)
            gout[c0 + tid] = aux[0][tid] + aux[1][tid];
        // barrier at top of next chunk's reduce protects tile reuse;
        // tile writes next chunk only conflict with reads already done
        __syncthreads();
    }
}

// ---------------- final: dsum + m + b_out ----------------
__global__ void k_final(const float* __restrict__ dec,
                        const float* __restrict__ hraw,
                        const float* __restrict__ mraw,
                        const float* __restrict__ oraw,
                        float* __restrict__ out) {
    __shared__ float sred[256];
    int tid = threadIdx.x;
    float a = 0.f;
    for (int i = tid; i < M_PTS; i += 256) a += g_density[i];
    sred[tid] = a;
    __syncthreads();
    for (int o = 128; o; o >>= 1) {
        if (tid < o) sred[tid] += sred[tid + o];
        __syncthreads();
    }
    float dsum = sred[0];

    int i = blockIdx.x*256 + tid;   // 0..16383
    int b = i >> 10, t = i & 1023;
    float acc = 0.f;
#pragma unroll
    for (int k = 0; k < NBLK_M; k++)
        acc += g_bpart[((size_t)b*NBLK_M + k)*TT + t];
    float mv = acc / dsum;
    float h = dec[i];
    float hs  = 10.f / (1.f + __expf(-hraw[0]));
    float ms  = 10.f / (1.f + __expf(-mraw[0]));
    float off = -10.f + 20.f / (1.f + __expf(-oraw[0]));
    out[OFF_BOUT + i] = hs*h + ms*mv + off;
    out[OFF_M + i] = mv;
}

// ---------------- launch ----------------
extern "C" void kernel_launch(void* const* d_in, const int* in_sizes, int n_in,
                              void* d_out, int out_size) {
    (void)in_sizes; (void)n_in; (void)out_size;
    const float* enc   = (const float*)d_in[0];
    const float* dec   = (const float*)d_in[1];
    const float* msk   = (const float*)d_in[2];
    const float* mesh  = (const float*)d_in[3];
    const float* dWin  = (const float*)d_in[4];
    const float* dbin  = (const float*)d_in[5];
    const float* dWr   = (const float*)d_in[6];
    const float* dbr   = (const float*)d_in[7];
    const float* dWout = (const float*)d_in[8];
    const float* dbout = (const float*)d_in[9];
    const float* eWs   = (const float*)d_in[10];
    const float* ebs   = (const float*)d_in[11];
    const float* eWm   = (const float*)d_in[12];
    const float* eWc   = (const float*)d_in[13];
    const float* ebm   = (const float*)d_in[14];
    const float* eWo   = (const float*)d_in[15];
    const float* ebo   = (const float*)d_in[16];
    const float* hraw  = (const float*)d_in[17];
    const float* mraw  = (const float*)d_in[18];
    const float* oraw  = (const float*)d_in[19];
    float* out = (float*)d_out;

    // density MLP
    k_dens_in<<<M_PTS, 256>>>(mesh, dWin, dbin);
    dim3 gres(81, 4);
    k_res<<<gres, 128>>>(dWr + 0*HIDN*HIDN, dbr + 0*HIDN, 0);  // x -> y
    k_res<<<gres, 128>>>(dWr + 1*HIDN*HIDN, dbr + 1*HIDN, 1);  // y -> x
    k_res<<<gres, 128>>>(dWr + 2*HIDN*HIDN, dbr + 2*HIDN, 0);  // x -> y
    k_dens_out<<<644, 256>>>(dWout, dbout);

    // encoder + initial states (+ density/mesh output replication)
    k_ctxw<<<BB, 256>>>(enc, msk, eWs, ebs, eWc);
    dim3 ginit(6, BB);
    k_init<<<ginit, 256>>>(mesh, eWm, ebm, eWo, ebo, out);

    // relay scan + final (final also computes dsum)
    dim3 gscan(NBLK_M, BB);
    k_scan<<<gscan, 128>>>(dec, mesh);
    k_final<<<64, 256>>>(dec, hraw, mraw, oraw, out);
}

// round 6
// speedup vs baseline: 1.4798x; 1.0334x over previous
#include <cuda_runtime.h>

#define M_PTS 5151
#define HIDN  256
#define BB    16
#define SS    256
#define TT    1024
#define GRID_N 101         // mesh grid points per axis
#define TDIM   16          // scan tile edge
#define NTILES 28          // upper-triangular 7x7 tiles
#define TC     32          // scan time-chunk
#define CUT 0.018f

// Output layout: concatenated (b_out, density, m, initial_states, mesh)
#define OFF_BOUT 0
#define OFF_D    16384                    // 16*1024
#define OFF_M    (OFF_D + BB*M_PTS)       // 98800
#define OFF_IS   (OFF_M + BB*TT)          // 115184
#define OFF_MESH (OFF_IS + BB*M_PTS)      // 197600

// ---------------- scratch (device globals; no allocation) ----------------
__device__ float g_x[5248*HIDN];
__device__ float g_y[5248*HIDN];
__device__ float g_density[M_PTS];
__device__ float g_cwc[BB*HIDN];
__device__ float g_init[BB*M_PTS];
__device__ float g_bpart[BB*NTILES*TT];

__device__ __forceinline__ float fast_tanh(float x) {
    float r;
    asm("tanh.approx.f32 %0, %1;" : "=f"(r) : "f"(x));
    return r;
}

// ---------------- density input layer: x = relu(mesh @ Win + bin) --------
__global__ void k_dens_in(const float* __restrict__ mesh,
                          const float* __restrict__ Win,
                          const float* __restrict__ bin) {
    int m = blockIdx.x;
    int j = threadIdx.x;
    float be = mesh[2*m], al = mesh[2*m+1];
    float v = be*Win[j] + al*Win[HIDN+j] + bin[j];
    g_x[m*HIDN + j] = fmaxf(v, 0.f);
}

// ---------------- residual layer: Y = X + relu(X @ W + b) ----------------
// 64x64 tile, BK=16, 128 threads, 8x4 micro-tile, register prefetch.
__global__ void __launch_bounds__(128) k_res(const float* __restrict__ W,
                                             const float* __restrict__ bias,
                                             int flip) {
    const float* X = flip ? g_y : g_x;
    float*       Y = flip ? g_x : g_y;

    __shared__ __align__(16) float As[16][68];   // [k][row]
    __shared__ __align__(16) float Bs[16][64];   // [k][col]

    int bm = blockIdx.x * 64, bn = blockIdx.y * 64;
    int tid = threadIdx.x;
    int tx = tid & 15;
    int ty = tid >> 4;

    float acc[8][4];
#pragma unroll
    for (int i = 0; i < 8; i++)
#pragma unroll
        for (int j = 0; j < 4; j++) acc[i][j] = 0.f;

    int arow = tid & 63;
    int acol = (tid >> 6) * 8;
    int gra  = bm + arow;
    bool av  = gra < M_PTS;
    const float* Xa = X + (size_t)(av ? gra : 0) * HIDN + acol;
    int bkr0 = tid >> 4;
    int bc   = (tid & 15) * 4;
    const float* Wb = W + (size_t)bkr0 * HIDN + bn + bc;

    float4 z4 = make_float4(0.f,0.f,0.f,0.f);
    float4 pa0 = av ? *(const float4*)(Xa + 0) : z4;
    float4 pa1 = av ? *(const float4*)(Xa + 4) : z4;
    float4 pb0 = *(const float4*)(Wb);
    float4 pb1 = *(const float4*)(Wb + 8*HIDN);

    for (int k0 = 0; k0 < HIDN; k0 += 16) {
        As[acol+0][arow] = pa0.x;
        As[acol+1][arow] = pa0.y;
        As[acol+2][arow] = pa0.z;
        As[acol+3][arow] = pa0.w;
        As[acol+4][arow] = pa1.x;
        As[acol+5][arow] = pa1.y;
        As[acol+6][arow] = pa1.z;
        As[acol+7][arow] = pa1.w;
        *(float4*)&Bs[bkr0    ][bc] = pb0;
        *(float4*)&Bs[bkr0 + 8][bc] = pb1;
        __syncthreads();

        if (k0 + 16 < HIDN) {
            const float* Xn = Xa + k0 + 16;
            const float* Wn = Wb + (size_t)(k0 + 16) * HIDN;
            pa0 = av ? *(const float4*)(Xn + 0) : z4;
            pa1 = av ? *(const float4*)(Xn + 4) : z4;
            pb0 = *(const float4*)(Wn);
            pb1 = *(const float4*)(Wn + 8*HIDN);
        }

#pragma unroll
        for (int kk = 0; kk < 16; kk++) {
            float4 a0 = *(const float4*)&As[kk][ty*8];
            float4 a1 = *(const float4*)&As[kk][ty*8 + 4];
            float4 b0 = *(const float4*)&Bs[kk][tx*4];
            float a[8] = {a0.x,a0.y,a0.z,a0.w,a1.x,a1.y,a1.z,a1.w};
            float b[4] = {b0.x,b0.y,b0.z,b0.w};
#pragma unroll
            for (int i = 0; i < 8; i++)
#pragma unroll
                for (int j = 0; j < 4; j++)
                    acc[i][j] = fmaf(a[i], b[j], acc[i][j]);
        }
        __syncthreads();
    }

    int gc0 = bn + tx*4;
    float4 bz = *(const float4*)&bias[gc0];
    float bv[4] = {bz.x, bz.y, bz.z, bz.w};
#pragma unroll
    for (int i = 0; i < 8; i++) {
        int gr = bm + ty*8 + i;
        if (gr < M_PTS) {
            float4 xv = *(const float4*)&X[gr*HIDN + gc0];
            float4 o;
            o.x = xv.x + fmaxf(acc[i][0] + bv[0], 0.f);
            o.y = xv.y + fmaxf(acc[i][1] + bv[1], 0.f);
            o.z = xv.z + fmaxf(acc[i][2] + bv[2], 0.f);
            o.w = xv.w + fmaxf(acc[i][3] + bv[3], 0.f);
            *(float4*)&Y[gr*HIDN + gc0] = o;
        }
    }
}

// ---------------- density output: sigmoid(x @ Wout + bout) ---------------
__global__ void k_dens_out(const float* __restrict__ Wout,
                           const float* __restrict__ bout) {
    int w = blockIdx.x*8 + (threadIdx.x >> 5);
    int lane = threadIdx.x & 31;
    if (w >= M_PTS) return;
    float acc = 0.f;
#pragma unroll
    for (int i = 0; i < 8; i++)
        acc += g_y[w*HIDN + lane + i*32] * Wout[lane + i*32];
#pragma unroll
    for (int o = 16; o; o >>= 1) acc += __shfl_xor_sync(0xffffffffu, acc, o);
    if (lane == 0) {
        float z = acc + bout[0];
        g_density[w] = 1.f / (1.f + __expf(-z));
    }
}

// ---------------- encoder ctx + ctx @ Wc (fused) ----------------
__global__ void k_ctxw(const float* __restrict__ enc,
                       const float* __restrict__ mask,
                       const float* __restrict__ Ws,
                       const float* __restrict__ bs,
                       const float* __restrict__ Wc) {
    int b = blockIdx.x;
    int j = threadIdx.x;
    __shared__ float se[2*SS];
    __shared__ float sm[SS];
    __shared__ float sctx[HIDN];
    for (int i = j; i < 2*SS; i += 256) se[i] = enc[b*2*SS + i];
    for (int i = j; i < SS;   i += 256) sm[i] = mask[b*SS + i];
    __syncthreads();
    float w0 = Ws[j], w1 = Ws[HIDN + j], bj = bs[j];
    float acc = 0.f, msum = 0.f;
    for (int s = 0; s < SS; s++) {
        float mk = sm[s];
        msum += mk;
        float v = fmaxf(se[2*s]*w0 + se[2*s+1]*w1 + bj, 0.f);
        acc += mk * v;
    }
    sctx[j] = acc / fmaxf(msum, 1.f);
    __syncthreads();
    float a2 = 0.f;
    for (int k = 0; k < HIDN; k++) a2 += sctx[k] * Wc[k*HIDN + j];
    g_cwc[b*HIDN + j] = a2;
}

// ------- initial states + density/mesh replication; 4 points/thread ------
__global__ void k_init(const float* __restrict__ mesh,
                       const float* __restrict__ Wm,
                       const float* __restrict__ bm,
                       const float* __restrict__ Wo,
                       const float* __restrict__ bo,
                       float* __restrict__ out) {
    int b = blockIdx.y;
    int j = threadIdx.x;
    __shared__ __align__(16) float sW0[HIDN], sW1[HIDN], sW2[HIDN], sWo[HIDN], sC[HIDN];
    sW0[j] = Wm[j];
    sW1[j] = Wm[HIDN + j];
    sW2[j] = Wm[2*HIDN + j];
    sWo[j] = Wo[j];
    sC[j]  = g_cwc[b*HIDN + j] + bm[j];
    __syncthreads();

    int m[4]; bool v[4];
    float be[4], al[4], d[4], acc[4];
#pragma unroll
    for (int q = 0; q < 4; q++) {
        m[q] = blockIdx.x*1024 + q*256 + j;
        v[q] = m[q] < M_PTS;
        int mm = v[q] ? m[q] : 0;
        be[q] = mesh[2*mm];
        al[q] = mesh[2*mm + 1];
        d[q]  = g_density[mm];
        acc[q] = 0.f;
    }

    const float4* w0 = (const float4*)sW0;
    const float4* w1 = (const float4*)sW1;
    const float4* w2 = (const float4*)sW2;
    const float4* wo = (const float4*)sWo;
    const float4* cc = (const float4*)sC;
#pragma unroll 2
    for (int qq = 0; qq < HIDN/4; qq++) {
        float4 a0 = w0[qq], a1 = w1[qq], a2 = w2[qq], ao = wo[qq], ac = cc[qq];
#pragma unroll
        for (int q = 0; q < 4; q++) {
            acc[q] += fmaxf(ac.x + be[q]*a0.x + al[q]*a1.x + d[q]*a2.x, 0.f) * ao.x;
            acc[q] += fmaxf(ac.y + be[q]*a0.y + al[q]*a1.y + d[q]*a2.y, 0.f) * ao.y;
            acc[q] += fmaxf(ac.z + be[q]*a0.z + al[q]*a1.z + d[q]*a2.z, 0.f) * ao.z;
            acc[q] += fmaxf(ac.w + be[q]*a0.w + al[q]*a1.w + d[q]*a2.w, 0.f) * ao.w;
        }
    }
    float bo0 = bo[0];
#pragma unroll
    for (int q = 0; q < 4; q++) {
        if (!v[q]) continue;
        float is = tanhf(acc[q] + bo0);
        g_init[b*M_PTS + m[q]] = is;
        out[OFF_IS + (size_t)b*M_PTS + m[q]] = is;
        out[OFF_D  + (size_t)b*M_PTS + m[q]] = d[q];
        ((float2*)out)[(OFF_MESH >> 1) + (size_t)b*M_PTS + m[q]] = make_float2(be[q], al[q]);
    }
}

// ------- relay scan: 2D triangle tiles (16beta x 16alpha), 256 thr -------
__global__ void __launch_bounds__(256) k_scan(const float* __restrict__ dec,
                                              const float* __restrict__ mesh) {
    __shared__ float sh_h[TT];
    __shared__ float tile[256*(TC+1)];
    __shared__ float aux[8][TC];
    int b = blockIdx.y;
    int tid = threadIdx.x;        // 0..255

    // map blockIdx.x (0..27) -> (tb, ta), ta >= tb, 7x7 upper triangle
    int tile_id = blockIdx.x;
    int tb = 0, rem = tile_id;
    while (rem >= 7 - tb) { rem -= 7 - tb; tb++; }
    int ta = tb + rem;

    int ib = tb*TDIM + (tid >> 4);     // beta index
    int ia = ta*TDIM + (tid & 15);     // alpha index
    bool valid = (ib < GRID_N) && (ia < GRID_N) && (ia >= ib);
    int idx = 0;
    if (valid) idx = ib*GRID_N - (ib*(ib-1))/2 + (ia - ib);

    for (int t = tid; t < TT; t += 256) sh_h[t] = dec[b*TT + t];

    float be = valid ? mesh[2*idx]     : -2.f;
    float al = valid ? mesh[2*idx + 1] :  2.f;
    float d  = valid ? g_density[idx]  :  0.f;
    float s  = valid ? g_init[b*M_PTS + idx] : 0.f;
    __syncthreads();

    float* myrow = &tile[tid*(TC+1)];
    int rcol  = tid & (TC-1);          // reduce column 0..31
    int rbase = (tid >> 5) * 32;       // reduce row group (8 groups of 32)
    float* gout = &g_bpart[((size_t)b*NTILES + blockIdx.x)*TT];

    for (int c0 = 0; c0 < TT; c0 += TC) {
#pragma unroll 4
        for (int tt = 0; tt < TC; tt++) {
            float ht = sh_h[c0 + tt];
            float xu = ht - al;
            float xd = be - ht;
            bool nearany = (fabsf(xu) < CUT) | (fabsf(xd) < CUT);
            if (__any_sync(0xffffffffu, nearany)) {
                float wu = 0.5f*fast_tanh(500.f*xu) + 0.5f;
                float wd = 0.5f*fast_tanh(500.f*xd) + 0.5f;
                s += wu * (1.f - s);
                s += wd * (-1.f - s);
            } else {
                if (xu > 0.f) s = 1.f;
                if (xd > 0.f) s = -1.f;
            }
            myrow[tt] = d * s;
        }
        __syncthreads();
        // reduce 256 rows x TC cols: each of 8 groups sums 32 rows of one col
        float a = 0.f;
#pragma unroll 8
        for (int i = 0; i < 32; i++)
            a += tile[(rbase + i)*(TC+1) + rcol];
        aux[tid >> 5][rcol] = a;
        __syncthreads();
        if (tid < TC) {
            float g = 0.f;
#pragma unroll
            for (int w = 0; w < 8; w++) g += aux[w][tid];
            gout[c0 + tid] = g;
        }
        __syncthreads();
    }
}

// ---------------- final: dsum + m + b_out ----------------
__global__ void k_final(const float* __restrict__ dec,
                        const float* __restrict__ hraw,
                        const float* __restrict__ mraw,
                        const float* __restrict__ oraw,
                        float* __restrict__ out) {
    __shared__ float sred[256];
    int tid = threadIdx.x;
    float a = 0.f;
    for (int i = tid; i < M_PTS; i += 256) a += g_density[i];
    sred[tid] = a;
    __syncthreads();
    for (int o = 128; o; o >>= 1) {
        if (tid < o) sred[tid] += sred[tid + o];
        __syncthreads();
    }
    float dsum = sred[0];

    int i = blockIdx.x*256 + tid;   // 0..16383
    int b = i >> 10, t = i & 1023;
    float acc = 0.f;
#pragma unroll
    for (int k = 0; k < NTILES; k++)
        acc += g_bpart[((size_t)b*NTILES + k)*TT + t];
    float mv = acc / dsum;
    float h = dec[i];
    float hs  = 10.f / (1.f + __expf(-hraw[0]));
    float ms  = 10.f / (1.f + __expf(-mraw[0]));
    float off = -10.f + 20.f / (1.f + __expf(-oraw[0]));
    out[OFF_BOUT + i] = hs*h + ms*mv + off;
    out[OFF_M + i] = mv;
}

// ---------------- launch ----------------
extern "C" void kernel_launch(void* const* d_in, const int* in_sizes, int n_in,
                              void* d_out, int out_size) {
    (void)in_sizes; (void)n_in; (void)out_size;
    const float* enc   = (const float*)d_in[0];
    const float* dec   = (const float*)d_in[1];
    const float* msk   = (const float*)d_in[2];
    const float* mesh  = (const float*)d_in[3];
    const float* dWin  = (const float*)d_in[4];
    const float* dbin  = (const float*)d_in[5];
    const float* dWr   = (const float*)d_in[6];
    const float* dbr   = (const float*)d_in[7];
    const float* dWout = (const float*)d_in[8];
    const float* dbout = (const float*)d_in[9];
    const float* eWs   = (const float*)d_in[10];
    const float* ebs   = (const float*)d_in[11];
    const float* eWm   = (const float*)d_in[12];
    const float* eWc   = (const float*)d_in[13];
    const float* ebm   = (const float*)d_in[14];
    const float* eWo   = (const float*)d_in[15];
    const float* ebo   = (const float*)d_in[16];
    const float* hraw  = (const float*)d_in[17];
    const float* mraw  = (const float*)d_in[18];
    const float* oraw  = (const float*)d_in[19];
    float* out = (float*)d_out;

    // density MLP
    k_dens_in<<<M_PTS, 256>>>(mesh, dWin, dbin);
    dim3 gres(81, 4);
    k_res<<<gres, 128>>>(dWr + 0*HIDN*HIDN, dbr + 0*HIDN, 0);  // x -> y
    k_res<<<gres, 128>>>(dWr + 1*HIDN*HIDN, dbr + 1*HIDN, 1);  // y -> x
    k_res<<<gres, 128>>>(dWr + 2*HIDN*HIDN, dbr + 2*HIDN, 0);  // x -> y
    k_dens_out<<<644, 256>>>(dWout, dbout);

    // encoder + initial states (+ density/mesh output replication)
    k_ctxw<<<BB, 256>>>(enc, msk, eWs, ebs, eWc);
    dim3 ginit(6, BB);
    k_init<<<ginit, 256>>>(mesh, eWm, ebm, eWo, ebo, out);

    // relay scan + final (final also computes dsum)
    dim3 gscan(NTILES, BB);
    k_scan<<<gscan, 256>>>(dec, mesh);
    k_final<<<64, 256>>>(dec, hraw, mraw, oraw, out);
}

// round 7
// speedup vs baseline: 1.6135x; 1.0903x over previous
#include <cuda_runtime.h>

#define M_PTS 5151
#define HIDN  256
#define BB    16
#define SS    256
#define TT    1024
#define GRID_N 101         // mesh grid points per axis
#define TDIM   16          // scan tile edge
#define NTILES 28          // upper-triangular 7x7 tiles
#define TC     32          // scan time-chunk
#define TSTR   36          // tile row stride (16B aligned, conflict-free)
#define CUT 0.018f

// Output layout: concatenated (b_out, density, m, initial_states, mesh)
#define OFF_BOUT 0
#define OFF_D    16384                    // 16*1024
#define OFF_M    (OFF_D + BB*M_PTS)       // 98800
#define OFF_IS   (OFF_M + BB*TT)          // 115184
#define OFF_MESH (OFF_IS + BB*M_PTS)      // 197600

// ---------------- scratch (device globals; no allocation) ----------------
__device__ float g_x[5248*HIDN];
__device__ float g_y[5248*HIDN];
__device__ float g_density[M_PTS];
__device__ float g_cwc[BB*HIDN];
__device__ float g_init[BB*M_PTS];
__device__ float g_bpart[BB*NTILES*TT];

__device__ __forceinline__ float fast_tanh(float x) {
    float r;
    asm("tanh.approx.f32 %0, %1;" : "=f"(r) : "f"(x));
    return r;
}

// packed f32x2 helpers (Blackwell)
#define PACK_DUP(d, s)   asm("mov.b64 %0, {%1, %1};" : "=l"(d) : "f"(s))
#define FMA2(acc, a, b)  asm("fma.rn.f32x2 %0, %1, %2, %0;" : "+l"(acc) : "l"(a), "l"(b))
#define UNPACK2(lo, hi, v) asm("mov.b64 {%0, %1}, %2;" : "=f"(lo), "=f"(hi) : "l"(v))

// ---------------- density input layer: x = relu(mesh @ Win + bin) --------
__global__ void k_dens_in(const float* __restrict__ mesh,
                          const float* __restrict__ Win,
                          const float* __restrict__ bin) {
    int m = blockIdx.x;
    int j = threadIdx.x;
    float be = mesh[2*m], al = mesh[2*m+1];
    float v = be*Win[j] + al*Win[HIDN+j] + bin[j];
    g_x[m*HIDN + j] = fmaxf(v, 0.f);
}

// ---------------- residual layer: Y = X + relu(X @ W + b) ----------------
// 64x64 tile, BK=16, 128 threads, 8x4 micro-tile via packed f32x2 FMA.
__global__ void __launch_bounds__(128) k_res(const float* __restrict__ W,
                                             const float* __restrict__ bias,
                                             int flip) {
    const float* X = flip ? g_y : g_x;
    float*       Y = flip ? g_x : g_y;

    __shared__ __align__(16) float As[16][68];   // [k][row]
    __shared__ __align__(16) float Bs[16][64];   // [k][col]

    int bm = blockIdx.x * 64, bn = blockIdx.y * 64;
    int tid = threadIdx.x;
    int tx = tid & 15;
    int ty = tid >> 4;

    // accp[r][j] packs output rows (2r, 2r+1) for column j
    unsigned long long accp[4][4];
#pragma unroll
    for (int r = 0; r < 4; r++)
#pragma unroll
        for (int j = 0; j < 4; j++) accp[r][j] = 0ull;

    int arow = tid & 63;
    int acol = (tid >> 6) * 8;
    int gra  = bm + arow;
    bool av  = gra < M_PTS;
    const float* Xa = X + (size_t)(av ? gra : 0) * HIDN + acol;
    int bkr0 = tid >> 4;
    int bc   = (tid & 15) * 4;
    const float* Wb = W + (size_t)bkr0 * HIDN + bn + bc;

    float4 z4 = make_float4(0.f,0.f,0.f,0.f);
    float4 pa0 = av ? *(const float4*)(Xa + 0) : z4;
    float4 pa1 = av ? *(const float4*)(Xa + 4) : z4;
    float4 pb0 = *(const float4*)(Wb);
    float4 pb1 = *(const float4*)(Wb + 8*HIDN);

    for (int k0 = 0; k0 < HIDN; k0 += 16) {
        As[acol+0][arow] = pa0.x;
        As[acol+1][arow] = pa0.y;
        As[acol+2][arow] = pa0.z;
        As[acol+3][arow] = pa0.w;
        As[acol+4][arow] = pa1.x;
        As[acol+5][arow] = pa1.y;
        As[acol+6][arow] = pa1.z;
        As[acol+7][arow] = pa1.w;
        *(float4*)&Bs[bkr0    ][bc] = pb0;
        *(float4*)&Bs[bkr0 + 8][bc] = pb1;
        __syncthreads();

        if (k0 + 16 < HIDN) {
            const float* Xn = Xa + k0 + 16;
            const float* Wn = Wb + (size_t)(k0 + 16) * HIDN;
            pa0 = av ? *(const float4*)(Xn + 0) : z4;
            pa1 = av ? *(const float4*)(Xn + 4) : z4;
            pb0 = *(const float4*)(Wn);
            pb1 = *(const float4*)(Wn + 8*HIDN);
        }

#pragma unroll
        for (int kk = 0; kk < 16; kk++) {
            // row pairs: (0,1)(2,3) from first 16B, (4,5)(6,7) from second
            ulonglong2 ra = *(const ulonglong2*)&As[kk][ty*8];
            ulonglong2 rb = *(const ulonglong2*)&As[kk][ty*8 + 4];
            float4 b0 = *(const float4*)&Bs[kk][tx*4];
            unsigned long long bd0, bd1, bd2, bd3;
            PACK_DUP(bd0, b0.x);
            PACK_DUP(bd1, b0.y);
            PACK_DUP(bd2, b0.z);
            PACK_DUP(bd3, b0.w);
            FMA2(accp[0][0], ra.x, bd0);
            FMA2(accp[0][1], ra.x, bd1);
            FMA2(accp[0][2], ra.x, bd2);
            FMA2(accp[0][3], ra.x, bd3);
            FMA2(accp[1][0], ra.y, bd0);
            FMA2(accp[1][1], ra.y, bd1);
            FMA2(accp[1][2], ra.y, bd2);
            FMA2(accp[1][3], ra.y, bd3);
            FMA2(accp[2][0], rb.x, bd0);
            FMA2(accp[2][1], rb.x, bd1);
            FMA2(accp[2][2], rb.x, bd2);
            FMA2(accp[2][3], rb.x, bd3);
            FMA2(accp[3][0], rb.y, bd0);
            FMA2(accp[3][1], rb.y, bd1);
            FMA2(accp[3][2], rb.y, bd2);
            FMA2(accp[3][3], rb.y, bd3);
        }
        __syncthreads();
    }

    // unpack accumulators
    float acc[8][4];
#pragma unroll
    for (int r = 0; r < 4; r++)
#pragma unroll
        for (int j = 0; j < 4; j++)
            UNPACK2(acc[2*r][j], acc[2*r+1][j], accp[r][j]);

    int gc0 = bn + tx*4;
    float4 bz = *(const float4*)&bias[gc0];
    float bv[4] = {bz.x, bz.y, bz.z, bz.w};
#pragma unroll
    for (int i = 0; i < 8; i++) {
        int gr = bm + ty*8 + i;
        if (gr < M_PTS) {
            float4 xv = *(const float4*)&X[gr*HIDN + gc0];
            float4 o;
            o.x = xv.x + fmaxf(acc[i][0] + bv[0], 0.f);
            o.y = xv.y + fmaxf(acc[i][1] + bv[1], 0.f);
            o.z = xv.z + fmaxf(acc[i][2] + bv[2], 0.f);
            o.w = xv.w + fmaxf(acc[i][3] + bv[3], 0.f);
            *(float4*)&Y[gr*HIDN + gc0] = o;
        }
    }
}

// ---------------- density output: sigmoid(x @ Wout + bout) ---------------
__global__ void k_dens_out(const float* __restrict__ Wout,
                           const float* __restrict__ bout) {
    int w = blockIdx.x*8 + (threadIdx.x >> 5);
    int lane = threadIdx.x & 31;
    if (w >= M_PTS) return;
    float acc = 0.f;
#pragma unroll
    for (int i = 0; i < 8; i++)
        acc += g_y[w*HIDN + lane + i*32] * Wout[lane + i*32];
#pragma unroll
    for (int o = 16; o; o >>= 1) acc += __shfl_xor_sync(0xffffffffu, acc, o);
    if (lane == 0) {
        float z = acc + bout[0];
        g_density[w] = 1.f / (1.f + __expf(-z));
    }
}

// ---------------- encoder ctx + ctx @ Wc (fused) ----------------
__global__ void k_ctxw(const float* __restrict__ enc,
                       const float* __restrict__ mask,
                       const float* __restrict__ Ws,
                       const float* __restrict__ bs,
                       const float* __restrict__ Wc) {
    int b = blockIdx.x;
    int j = threadIdx.x;
    __shared__ float se[2*SS];
    __shared__ float sm[SS];
    __shared__ float sctx[HIDN];
    for (int i = j; i < 2*SS; i += 256) se[i] = enc[b*2*SS + i];
    for (int i = j; i < SS;   i += 256) sm[i] = mask[b*SS + i];
    __syncthreads();
    float w0 = Ws[j], w1 = Ws[HIDN + j], bj = bs[j];
    float acc = 0.f, msum = 0.f;
    for (int s = 0; s < SS; s++) {
        float mk = sm[s];
        msum += mk;
        float v = fmaxf(se[2*s]*w0 + se[2*s+1]*w1 + bj, 0.f);
        acc += mk * v;
    }
    sctx[j] = acc / fmaxf(msum, 1.f);
    __syncthreads();
    float a2 = 0.f;
    for (int k = 0; k < HIDN; k++) a2 += sctx[k] * Wc[k*HIDN + j];
    g_cwc[b*HIDN + j] = a2;
}

// ------- initial states + density/mesh replication; 4 points/thread ------
__global__ void k_init(const float* __restrict__ mesh,
                       const float* __restrict__ Wm,
                       const float* __restrict__ bm,
                       const float* __restrict__ Wo,
                       const float* __restrict__ bo,
                       float* __restrict__ out) {
    int b = blockIdx.y;
    int j = threadIdx.x;
    __shared__ __align__(16) float sW0[HIDN], sW1[HIDN], sW2[HIDN], sWo[HIDN], sC[HIDN];
    sW0[j] = Wm[j];
    sW1[j] = Wm[HIDN + j];
    sW2[j] = Wm[2*HIDN + j];
    sWo[j] = Wo[j];
    sC[j]  = g_cwc[b*HIDN + j] + bm[j];
    __syncthreads();

    int m[4]; bool v[4];
    float be[4], al[4], d[4], acc[4];
#pragma unroll
    for (int q = 0; q < 4; q++) {
        m[q] = blockIdx.x*1024 + q*256 + j;
        v[q] = m[q] < M_PTS;
        int mm = v[q] ? m[q] : 0;
        be[q] = mesh[2*mm];
        al[q] = mesh[2*mm + 1];
        d[q]  = g_density[mm];
        acc[q] = 0.f;
    }

    const float4* w0 = (const float4*)sW0;
    const float4* w1 = (const float4*)sW1;
    const float4* w2 = (const float4*)sW2;
    const float4* wo = (const float4*)sWo;
    const float4* cc = (const float4*)sC;
#pragma unroll 2
    for (int qq = 0; qq < HIDN/4; qq++) {
        float4 a0 = w0[qq], a1 = w1[qq], a2 = w2[qq], ao = wo[qq], ac = cc[qq];
#pragma unroll
        for (int q = 0; q < 4; q++) {
            acc[q] += fmaxf(ac.x + be[q]*a0.x + al[q]*a1.x + d[q]*a2.x, 0.f) * ao.x;
            acc[q] += fmaxf(ac.y + be[q]*a0.y + al[q]*a1.y + d[q]*a2.y, 0.f) * ao.y;
            acc[q] += fmaxf(ac.z + be[q]*a0.z + al[q]*a1.z + d[q]*a2.z, 0.f) * ao.z;
            acc[q] += fmaxf(ac.w + be[q]*a0.w + al[q]*a1.w + d[q]*a2.w, 0.f) * ao.w;
        }
    }
    float bo0 = bo[0];
#pragma unroll
    for (int q = 0; q < 4; q++) {
        if (!v[q]) continue;
        float is = tanhf(acc[q] + bo0);
        g_init[b*M_PTS + m[q]] = is;
        out[OFF_IS + (size_t)b*M_PTS + m[q]] = is;
        out[OFF_D  + (size_t)b*M_PTS + m[q]] = d[q];
        ((float2*)out)[(OFF_MESH >> 1) + (size_t)b*M_PTS + m[q]] = make_float2(be[q], al[q]);
    }
}

// ------- relay scan: 2D triangle tiles (16beta x 16alpha), 256 thr -------
// state sg = d*s tracked directly; float4 h loads; float4 STS per 4 steps.
__global__ void __launch_bounds__(256) k_scan(const float* __restrict__ dec,
                                              const float* __restrict__ mesh) {
    __shared__ __align__(16) float sh_h[TT];
    __shared__ __align__(16) float tile[256*TSTR];
    __shared__ float aux[8][TC];
    int b = blockIdx.y;
    int tid = threadIdx.x;        // 0..255

    // map blockIdx.x (0..27) -> (tb, ta), ta >= tb, 7x7 upper triangle
    int tile_id = blockIdx.x;
    int tb = 0, rem = tile_id;
    while (rem >= 7 - tb) { rem -= 7 - tb; tb++; }
    int ta = tb + rem;

    int ib = tb*TDIM + (tid >> 4);     // beta index
    int ia = ta*TDIM + (tid & 15);     // alpha index
    bool valid = (ib < GRID_N) && (ia < GRID_N) && (ia >= ib);
    int idx = 0;
    if (valid) idx = ib*GRID_N - (ib*(ib-1))/2 + (ia - ib);

    for (int t = tid; t < TT; t += 256) sh_h[t] = dec[b*TT + t];

    float be = valid ? mesh[2*idx]     : -2.f;
    float al = valid ? mesh[2*idx + 1] :  2.f;
    float d  = valid ? g_density[idx]  :  0.f;
    float sg = valid ? d * g_init[b*M_PTS + idx] : 0.f;   // sg = d*s
    float nd = -d;
    __syncthreads();

    float* myrow = &tile[tid*TSTR];
    int rcol  = tid & (TC-1);          // reduce column 0..31
    int rbase = (tid >> 5) * 32;       // reduce row group (8 groups of 32)
    float* gout = &g_bpart[((size_t)b*NTILES + blockIdx.x)*TT];

    for (int c0 = 0; c0 < TT; c0 += TC) {
#pragma unroll 2
        for (int t4 = 0; t4 < TC; t4 += 4) {
            float4 h4 = *(const float4*)&sh_h[c0 + t4];
            float o[4];
            float hts[4] = {h4.x, h4.y, h4.z, h4.w};
#pragma unroll
            for (int u = 0; u < 4; u++) {
                float ht = hts[u];
                float xu = ht - al;
                float xd = be - ht;
                bool nearany = (fabsf(xu) < CUT) | (fabsf(xd) < CUT);
                if (__any_sync(0xffffffffu, nearany)) {
                    float wu = 0.5f*fast_tanh(500.f*xu) + 0.5f;
                    float wd = 0.5f*fast_tanh(500.f*xd) + 0.5f;
                    sg += wu * (d  - sg);
                    sg += wd * (nd - sg);
                } else {
                    if (xu > 0.f) sg = d;
                    if (xd > 0.f) sg = nd;
                }
                o[u] = sg;
            }
            *(float4*)&myrow[t4] = make_float4(o[0], o[1], o[2], o[3]);
        }
        __syncthreads();
        // reduce 256 rows x TC cols: each of 8 groups sums 32 rows of one col
        float a = 0.f;
#pragma unroll 8
        for (int i = 0; i < 32; i++)
            a += tile[(rbase + i)*TSTR + rcol];
        aux[tid >> 5][rcol] = a;
        __syncthreads();
        if (tid < TC) {
            float g = 0.f;
#pragma unroll
            for (int w = 0; w < 8; w++) g += aux[w][tid];
            gout[c0 + tid] = g;
        }
        __syncthreads();
    }
}

// ---------------- final: dsum + m + b_out ----------------
__global__ void k_final(const float* __restrict__ dec,
                        const float* __restrict__ hraw,
                        const float* __restrict__ mraw,
                        const float* __restrict__ oraw,
                        float* __restrict__ out) {
    __shared__ float sred[256];
    int tid = threadIdx.x;
    float a = 0.f;
    for (int i = tid; i < M_PTS; i += 256) a += g_density[i];
    sred[tid] = a;
    __syncthreads();
    for (int o = 128; o; o >>= 1) {
        if (tid < o) sred[tid] += sred[tid + o];
        __syncthreads();
    }
    float dsum = sred[0];

    int i = blockIdx.x*256 + tid;   // 0..16383
    int b = i >> 10, t = i & 1023;
    float acc = 0.f;
#pragma unroll
    for (int k = 0; k < NTILES; k++)
        acc += g_bpart[((size_t)b*NTILES + k)*TT + t];
    float mv = acc / dsum;
    float h = dec[i];
    float hs  = 10.f / (1.f + __expf(-hraw[0]));
    float ms  = 10.f / (1.f + __expf(-mraw[0]));
    float off = -10.f + 20.f / (1.f + __expf(-oraw[0]));
    out[OFF_BOUT + i] = hs*h + ms*mv + off;
    out[OFF_M + i] = mv;
}

// ---------------- launch ----------------
extern "C" void kernel_launch(void* const* d_in, const int* in_sizes, int n_in,
                              void* d_out, int out_size) {
    (void)in_sizes; (void)n_in; (void)out_size;
    const float* enc   = (const float*)d_in[0];
    const float* dec   = (const float*)d_in[1];
    const float* msk   = (const float*)d_in[2];
    const float* mesh  = (const float*)d_in[3];
    const float* dWin  = (const float*)d_in[4];
    const float* dbin  = (const float*)d_in[5];
    const float* dWr   = (const float*)d_in[6];
    const float* dbr   = (const float*)d_in[7];
    const float* dWout = (const float*)d_in[8];
    const float* dbout = (const float*)d_in[9];
    const float* eWs   = (const float*)d_in[10];
    const float* ebs   = (const float*)d_in[11];
    const float* eWm   = (const float*)d_in[12];
    const float* eWc   = (const float*)d_in[13];
    const float* ebm   = (const float*)d_in[14];
    const float* eWo   = (const float*)d_in[15];
    const float* ebo   = (const float*)d_in[16];
    const float* hraw  = (const float*)d_in[17];
    const float* mraw  = (const float*)d_in[18];
    const float* oraw  = (const float*)d_in[19];
    float* out = (float*)d_out;

    // density MLP
    k_dens_in<<<M_PTS, 256>>>(mesh, dWin, dbin);
    dim3 gres(81, 4);
    k_res<<<gres, 128>>>(dWr + 0*HIDN*HIDN, dbr + 0*HIDN, 0);  // x -> y
    k_res<<<gres, 128>>>(dWr + 1*HIDN*HIDN, dbr + 1*HIDN, 1);  // y -> x
    k_res<<<gres, 128>>>(dWr + 2*HIDN*HIDN, dbr + 2*HIDN, 0);  // x -> y
    k_dens_out<<<644, 256>>>(dWout, dbout);

    // encoder + initial states (+ density/mesh output replication)
    k_ctxw<<<BB, 256>>>(enc, msk, eWs, ebs, eWc);
    dim3 ginit(6, BB);
    k_init<<<ginit, 256>>>(mesh, eWm, ebm, eWo, ebo, out);

    // relay scan + final (final also computes dsum)
    dim3 gscan(NTILES, BB);
    k_scan<<<gscan, 256>>>(dec, mesh);
    k_final<<<64, 256>>>(dec, hraw, mraw, oraw, out);
}